// round 17
// baseline (speedup 1.0000x reference)
#include <cuda_runtime.h>

#define B_   2048
#define T_   128
#define S_   256
#define H_   64
#define E_   32
#define V_   29
#define G4   256   // 4*H
#define ES   68    // enc SMEM row stride; halves at +0 and +34 (conflict-free)

typedef unsigned long long ull;

struct __align__(16) Smem {
    float enc0[S_ * ES];       // 69632 B
    float enc1[S_ * ES];       // 69632 B
    float gate_emb[V_ * G4];   // PERMUTED: [v][ (r&15)*16 + (r>>4) ] = W_ih[r,:32]@emb[v]+bias[r]
    float fcW[32 * 128];       // (rows 29..31 unused)
    float embS[V_ * E_];       // prologue only
    float scores0[S_], scores1[S_];
    float part0[16 * 64], part1[16 * 64];
    float bias[G4];            // prologue only
    float comb0[128], comb1[128];   // [0:64)=h [64:128)=ctx
    float hdup0[72], hdup1[72];     // h halves at 0 / 40 (bank offset)
    float cdup0[72], cdup1[72];     // ctx halves at 0 / 40
    float fcb[32];
    float redsum0[16], redsum1[16];
    int   ytok0[T_], ytok1[T_];
};

__device__ __forceinline__ ull pack2(float lo, float hi) {
    ull r; asm("mov.b64 %0, {%1, %2};" : "=l"(r) : "f"(lo), "f"(hi)); return r;
}
__device__ __forceinline__ ull fma2(ull a, ull b, ull c) {
    ull d; asm("fma.rn.f32x2 %0, %1, %2, %3;" : "=l"(d) : "l"(a), "l"(b), "l"(c));
    return d;
}
__device__ __forceinline__ float2 unpack2(ull v) {
    float lo, hi; asm("mov.b64 {%0, %1}, %2;" : "=f"(lo), "=f"(hi) : "l"(v));
    return make_float2(lo, hi);
}
__device__ __forceinline__ float sigmoid_(float z) {
    return 1.0f / (1.0f + __expf(-z));
}
__device__ __forceinline__ float tanh_(float x) {
    return 1.0f - 2.0f / (__expf(2.0f * x) + 1.0f);
}

// ---- P1: e_s = exp(enc[s,:].h), 2 threads/s (R3/R16-verified) ----
__device__ __forceinline__ void phase1(const float* __restrict__ enc,
                                       const float* __restrict__ hdup,
                                       float* __restrict__ scores,
                                       float* __restrict__ redsum,
                                       int r, int half, int lane, int wrp)
{
    const ull* ep = reinterpret_cast<const ull*>(enc + r * ES + half * 34);
    const ull* hp = reinterpret_cast<const ull*>(hdup + half * 40);
    ull a0 = 0ull, a1 = 0ull;
    #pragma unroll
    for (int k = 0; k < 16; k += 2) {
        a0 = fma2(ep[k],     hp[k],     a0);
        a1 = fma2(ep[k + 1], hp[k + 1], a1);
    }
    float2 fa = unpack2(a0), fb = unpack2(a1);
    float sc = (fa.x + fa.y) + (fb.x + fb.y);
    sc += __shfl_xor_sync(0xffffffffu, sc, 1);
    float e = __expf(sc);                   // |sc| bounded: no overflow
    if (half == 0) scores[r] = e;
    float su = e;
    #pragma unroll
    for (int o = 16; o > 1; o >>= 1)
        su += __shfl_xor_sync(0xffffffffu, su, o);
    if (lane == 0) redsum[wrp] = su;        // warp's 16 distinct scores
}

// ---- P3: context partials, warp q handles 16 s-rows (R3/R16-verified) ----
__device__ __forceinline__ void phase3(const float* __restrict__ enc,
                                       const float* __restrict__ scores,
                                       float* __restrict__ part,
                                       int wrp, int lane)
{
    const int sbase = wrp * 16;
    const float*  ebase = enc + sbase * ES + 2 * lane + ((lane >> 4) & 1) * 2;
    const float4* sp = reinterpret_cast<const float4*>(scores + sbase);
    float ax = 0.f, ay = 0.f;
    #pragma unroll
    for (int c = 0; c < 4; c++) {
        float4 sv = sp[c];
        float2 e0 = *reinterpret_cast<const float2*>(ebase + (4*c + 0) * ES);
        float2 e1 = *reinterpret_cast<const float2*>(ebase + (4*c + 1) * ES);
        float2 e2 = *reinterpret_cast<const float2*>(ebase + (4*c + 2) * ES);
        float2 e3 = *reinterpret_cast<const float2*>(ebase + (4*c + 3) * ES);
        ax += sv.x * e0.x; ay += sv.x * e0.y;
        ax += sv.y * e1.x; ay += sv.y * e1.y;
        ax += sv.z * e2.x; ay += sv.z * e2.y;
        ax += sv.w * e3.x; ay += sv.w * e3.y;
    }
    *reinterpret_cast<float2*>(&part[wrp * 64 + 2 * lane]) = make_float2(ax, ay);
}

// ---- ctx reduce + normalize (R16-verified) ----
__device__ __forceinline__ void ctx_reduce(const float* __restrict__ redsum,
                                           const float* __restrict__ part,
                                           float* __restrict__ comb,
                                           float* __restrict__ cdup, int j)
{
    float ssum = 0.f;
    #pragma unroll
    for (int k = 0; k < 16; k++) ssum += redsum[k];
    float inv = 1.0f / ssum;
    float ctx = 0.f;
    #pragma unroll
    for (int q = 0; q < 16; q++) ctx += part[q * 64 + j];
    ctx *= inv;
    comb[H_ + j] = ctx;
    cdup[j + ((j >> 5) << 3)] = ctx;   // halves at 0 / 40
}

// ---- half of a gate dot: w2[16] (32 floats) . vec (32 floats, bank-offset dup) ----
__device__ __forceinline__ void dot32(const float* __restrict__ dup, int half,
                                      const ull* __restrict__ w2,
                                      ull& a0, ull& a1)
{
    const float4* vp = reinterpret_cast<const float4*>(dup + 40 * half);
    #pragma unroll
    for (int k = 0; k < 8; k++) {
        float4 xv = vp[k];
        a0 = fma2(w2[2*k],   pack2(xv.x, xv.y), a0);
        a1 = fma2(w2[2*k+1], pack2(xv.z, xv.w), a1);
    }
}

__device__ __forceinline__ float hsum2(ull a0, ull a1) {
    float2 fa = unpack2(a0), fb = unpack2(a1);
    return (fa.x + fa.y) + (fb.x + fb.y);
}

// ---- P6: logits, 16 threads per vocab row (R3/R16-verified) ----
__device__ __forceinline__ void phase6(const float* __restrict__ fcW,
                                       const float* __restrict__ comb,
                                       const float* __restrict__ fcb,
                                       float* __restrict__ outp_t, int tid)
{
    int v = tid >> 4, p = tid & 15;
    float acc = 0.0f;
    if (v < V_) {
        const float4* fw = reinterpret_cast<const float4*>(fcW + v * 128 + p * 8);
        const float4* cb = reinterpret_cast<const float4*>(comb + p * 8);
        float4 w0 = fw[0], w1 = fw[1];
        float4 c0v = cb[0], c1v = cb[1];
        acc = w0.x*c0v.x + w0.y*c0v.y + w0.z*c0v.z + w0.w*c0v.w
            + w1.x*c1v.x + w1.y*c1v.y + w1.z*c1v.z + w1.w*c1v.w;
    }
    #pragma unroll
    for (int o = 8; o; o >>= 1)
        acc += __shfl_xor_sync(0xffffffffu, acc, o);
    if (p == 0 && v < V_)
        outp_t[v] = acc + fcb[v];
}

extern "C" __global__ void __launch_bounds__(512, 1)
decoder_persist_kernel(const int* __restrict__ y,
                       const float* __restrict__ h0,
                       const float* __restrict__ c0,
                       const float* __restrict__ enc_g,
                       const float* __restrict__ embt,
                       const float* __restrict__ Wih,
                       const float* __restrict__ Whh,
                       const float* __restrict__ bih,
                       const float* __restrict__ bhh,
                       const float* __restrict__ fcWg,
                       const float* __restrict__ fcbg,
                       float* __restrict__ out)
{
    extern __shared__ __align__(16) char smem_raw[];
    Smem& sm = *reinterpret_cast<Smem*>(smem_raw);
    const int tid  = threadIdx.x;
    const int b0   = 2 * blockIdx.x;
    const int b1   = b0 + 1;
    const int lane = tid & 31;
    const int wrp  = tid >> 5;
    const int r    = tid >> 1;           // P1 score row / prologue ge row
    const int half = tid & 1;
    const int k4   = lane >> 1;          // 0..15
    const int r4   = wrp + (k4 << 4);    // P4 gate row: unit gates i/f/g/o of
                                         // j = wrp+16m land in THIS warp.

    // ---- per-thread gate weights for row r4 (64 regs), shared by batches ----
    ull wihc2[16], whh2[16];
    {
        const float4* wi = reinterpret_cast<const float4*>(Wih + r4 * 96 + 32 + 32 * half);
        #pragma unroll
        for (int k = 0; k < 8; k++) {
            float4 v = wi[k];
            wihc2[2*k]   = pack2(v.x, v.y);
            wihc2[2*k+1] = pack2(v.z, v.w);
        }
        const float4* wh = reinterpret_cast<const float4*>(Whh + r4 * 64 + 32 * half);
        #pragma unroll
        for (int k = 0; k < 8; k++) {
            float4 v = wh[k];
            whh2[2*k]   = pack2(v.x, v.y);
            whh2[2*k+1] = pack2(v.z, v.w);
        }
    }

    // ---- stage both enc slices + constants ----
    {
        const float2* e0 = reinterpret_cast<const float2*>(enc_g + (size_t)b0 * (S_ * H_));
        const float2* e1 = reinterpret_cast<const float2*>(enc_g + (size_t)b1 * (S_ * H_));
        for (int i2 = tid; i2 < (S_ * H_) / 2; i2 += 512) {
            int s  = i2 >> 5;
            int h2 = (i2 & 31) << 1;
            int dst = s * ES + h2 + ((h2 >= 32) ? 2 : 0);
            *reinterpret_cast<float2*>(&sm.enc0[dst]) = e0[i2];
            *reinterpret_cast<float2*>(&sm.enc1[dst]) = e1[i2];
        }
    }
    for (int i = tid; i < V_ * 128; i += 512) sm.fcW[i] = fcWg[i];
    for (int i = tid; i < V_ * E_;  i += 512) sm.embS[i] = embt[i];
    if (tid < G4) sm.bias[tid] = bih[tid] + bhh[tid];
    if (tid < V_) sm.fcb[tid]  = fcbg[tid];
    if (tid < T_) { sm.ytok0[tid] = y[b0 * T_ + tid]; sm.ytok1[tid] = y[b1 * T_ + tid]; }
    if (tid < H_) {
        float hv = h0[b0 * H_ + tid];
        sm.comb0[tid] = hv;
        sm.hdup0[tid + ((tid >> 5) << 3)] = hv;
    } else if (tid < 2 * H_) {
        int j = tid - H_;
        float hv = h0[b1 * H_ + j];
        sm.comb1[j] = hv;
        sm.hdup1[j + ((j >> 5) << 3)] = hv;
    }
    // cell state lives in lanes 0,2,4,6 of every warp: unit j = wrp + 16*(lane/2)
    float creg0 = 0.0f, creg1 = 0.0f;
    if (lane < 8 && (lane & 1) == 0) {
        int j = wrp + ((lane >> 1) << 4);
        creg0 = c0[b0 * H_ + j];
        creg1 = c0[b1 * H_ + j];
    }
    __syncthreads();

    // ---- prologue: gate_emb (PERMUTED) [v][(r&15)*16 + (r>>4)] ----
    {
        float4 we[4];
        const float4* wg = reinterpret_cast<const float4*>(Wih + r * 96 + 16 * half);
        #pragma unroll
        for (int k = 0; k < 4; k++) we[k] = wg[k];
        float brow = sm.bias[r];
        const int pidx = ((r & 15) << 4) + (r >> 4);
        for (int v = 0; v < V_; v++) {
            const float4* em = reinterpret_cast<const float4*>(sm.embS + v * E_ + 16 * half);
            float a = 0.f;
            #pragma unroll
            for (int k = 0; k < 4; k++) {
                float4 e = em[k];
                a += we[k].x*e.x + we[k].y*e.y + we[k].z*e.z + we[k].w*e.w;
            }
            a += __shfl_xor_sync(0xffffffffu, a, 1);
            if (half == 0) sm.gate_emb[v * G4 + pidx] = a + brow;
        }
    }
    __syncthreads();

    float* outp0 = out + (size_t)b0 * T_ * V_;
    float* outp1 = out + (size_t)b1 * T_ * V_;

    for (int t = 0; t < T_; t++) {
        // ---- region 1: P1 + P3 for both batches ----
        phase1(sm.enc0, sm.hdup0, sm.scores0, sm.redsum0, r, half, lane, wrp);
        phase1(sm.enc1, sm.hdup1, sm.scores1, sm.redsum1, r, half, lane, wrp);
        __syncwarp();   // P3 reads only this warp's scores
        phase3(sm.enc0, sm.scores0, sm.part0, wrp, lane);
        phase3(sm.enc1, sm.scores1, sm.part1, wrp, lane);
        __syncthreads();  // bar_A: part*, redsum*

        // ---- region 2: W_hh@h partials (ALL warps) + ctx reduce (warps 0-3) ----
        ull h0a = 0ull, h0b = 0ull, h1a = 0ull, h1b = 0ull;
        dot32(sm.hdup0, half, whh2, h0a, h0b);
        dot32(sm.hdup1, half, whh2, h1a, h1b);
        if (tid < H_)
            ctx_reduce(sm.redsum0, sm.part0, sm.comb0, sm.cdup0, tid);
        else if (tid < 2 * H_)
            ctx_reduce(sm.redsum1, sm.part1, sm.comb1, sm.cdup1, tid - H_);
        __syncthreads();  // bar_B: ctx*

        // ---- region 3: ctx half of gates + in-warp gather + LSTM cells ----
        {
            ull a0 = h0a, a1 = h0b;
            dot32(sm.cdup0, half, wihc2, a0, a1);
            float g0 = hsum2(a0, a1);
            g0 += __shfl_xor_sync(0xffffffffu, g0, 1);   // all lanes: row r4 gate, b0

            ull c0a = h1a, c1b = h1b;
            dot32(sm.cdup1, half, wihc2, c0a, c1b);
            float g1 = hsum2(c0a, c1b);
            g1 += __shfl_xor_sync(0xffffffffu, g1, 1);   // row r4 gate, b1

            // add gate_emb (permuted: row r4 at word wrp*16 + k4)
            g0 += sm.gate_emb[sm.ytok0[t] * G4 + (wrp << 4) + k4];
            g1 += sm.gate_emb[sm.ytok1[t] * G4 + (wrp << 4) + k4];

            // gather f/g/o gates from lanes +8/+16/+24 (i = own value)
            float f0 = __shfl_sync(0xffffffffu, g0, (lane + 8)  & 31);
            float q0 = __shfl_sync(0xffffffffu, g0, (lane + 16) & 31);
            float o0 = __shfl_sync(0xffffffffu, g0, (lane + 24) & 31);
            float f1 = __shfl_sync(0xffffffffu, g1, (lane + 8)  & 31);
            float q1 = __shfl_sync(0xffffffffu, g1, (lane + 16) & 31);
            float o1 = __shfl_sync(0xffffffffu, g1, (lane + 24) & 31);

            if (lane < 8 && (lane & 1) == 0) {   // lanes 0,2,4,6: unit j
                int j  = wrp + ((lane >> 1) << 4);
                int jd = j + ((j >> 5) << 3);
                creg0 = sigmoid_(f0) * creg0 + sigmoid_(g0) * tanh_(q0);
                float hn0 = sigmoid_(o0) * tanh_(creg0);
                sm.comb0[j] = hn0;  sm.hdup0[jd] = hn0;
                creg1 = sigmoid_(f1) * creg1 + sigmoid_(g1) * tanh_(q1);
                float hn1 = sigmoid_(o1) * tanh_(creg1);
                sm.comb1[j] = hn1;  sm.hdup1[jd] = hn1;
            }
        }
        __syncthreads();  // bar_C: h*

        // ---- region 4: P6 logits for both batches ----
        phase6(sm.fcW, sm.comb0, sm.fcb, outp0 + t * V_, tid);
        phase6(sm.fcW, sm.comb1, sm.fcb, outp1 + t * V_, tid);
        // no trailing barrier: comb*/hdup*/cdup* are next written in regions
        // 2/3 of step t+1, each behind >=1 block barrier that all warps
        // (hence all finished P6s) must reach first.
    }
}

extern "C" void kernel_launch(void* const* d_in, const int* in_sizes, int n_in,
                              void* d_out, int out_size) {
    const int*   y    = (const int*)d_in[0];
    const float* h0   = (const float*)d_in[1];
    const float* c0   = (const float*)d_in[2];
    const float* enc  = (const float*)d_in[3];
    const float* emb  = (const float*)d_in[4];
    const float* Wih  = (const float*)d_in[5];
    const float* Whh  = (const float*)d_in[6];
    const float* bih  = (const float*)d_in[7];
    const float* bhh  = (const float*)d_in[8];
    const float* fcW  = (const float*)d_in[9];
    const float* fcb  = (const float*)d_in[10];
    float* out = (float*)d_out;

    size_t smem = sizeof(Smem);
    cudaFuncSetAttribute(decoder_persist_kernel,
                         cudaFuncAttributeMaxDynamicSharedMemorySize, (int)smem);
    decoder_persist_kernel<<<B_ / 2, 512, smem>>>(y, h0, c0, enc, emb,
                                                  Wih, Whh, bih, bhh, fcW, fcb, out);
}